// round 13
// baseline (speedup 1.0000x reference)
#include <cuda_runtime.h>
#include <cuda_bf16.h>
#include <cstdint>
#include <cstddef>

// ---------------------------------------------------------------------------
// QNetwork: GRU cell + 2-layer MLP head, B=65536
//   sa = [state|action]  (B,320)
//   gi = sa @ w_ih^T     (B,1536)
//   gh = h  @ w_hh^T     (B,1536)
//   r = sig(i_r+h_r+b), z = sig(i_z+h_z+b), n = tanh(i_n+b + r*(h_n+b))
//   h_new = (1-z)*n + z*h
//   x1 = relu(h_new@w1^T+b1); x2 = relu(x1@w2^T+b2); q = x2@w3^T+b3
// Outputs (flattened tuple concat): q (65536 floats) then h_new (65536*512).
// ---------------------------------------------------------------------------

#define BATCH   65536
#define SDIM    256
#define ADIM    64
#define INDIM   320
#define GDIM    512
#define HDIM    1024
#define G3      1536

// Scratch (no cudaMalloc allowed -> __device__ globals)
__device__ float g_sa[(size_t)BATCH * INDIM];
__device__ float g_gi[(size_t)BATCH * G3];
__device__ float g_gh[(size_t)BATCH * G3];
__device__ float g_x1[(size_t)BATCH * HDIM];
__device__ float g_x2[(size_t)BATCH * HDIM];

// ---------------- f32x2 packed-FMA helpers (FFMA2 path, sm_103a) ----------
__device__ __forceinline__ unsigned long long pk2(float lo, float hi) {
    unsigned long long r;
    asm("mov.b64 %0, {%1, %2};"
        : "=l"(r) : "r"(__float_as_uint(lo)), "r"(__float_as_uint(hi)));
    return r;
}
__device__ __forceinline__ void upk2(unsigned long long v, float& lo, float& hi) {
    unsigned int a, b;
    asm("mov.b64 {%0, %1}, %2;" : "=r"(a), "=r"(b) : "l"(v));
    lo = __uint_as_float(a);
    hi = __uint_as_float(b);
}
__device__ __forceinline__ void fma2(unsigned long long& d,
                                     unsigned long long a,
                                     unsigned long long b) {
    asm("fma.rn.f32x2 %0, %1, %2, %0;" : "+l"(d) : "l"(a), "l"(b));
}

// ---------------------------------------------------------------------------
// SGEMM (NT): C[M,N] = A[M,K] @ W[N,K]^T (+bias, +relu)
// BM=BN=128, BK=8, 256 threads, 8x8 microtile, double-buffered smem,
// inner product via packed f32x2 FMA (2 MACs / instr).
// Requires: M%128==0, N%128==0, K%8==0.
// ---------------------------------------------------------------------------
template <bool BIAS, bool RELU>
__global__ __launch_bounds__(256, 2)
void sgemm_nt(const float* __restrict__ A, const float* __restrict__ W,
              const float* __restrict__ bias, float* __restrict__ C,
              int M, int N, int K)
{
    __shared__ float As[2][8][132];
    __shared__ float Bs[2][8][132];

    const int tid = threadIdx.x;
    const int m0  = blockIdx.y * 128;
    const int n0  = blockIdx.x * 128;

    // gmem staging: each thread loads one float4 of A and one of W per tile
    const int ldRow = tid >> 1;          // 0..127
    const int ldCol = (tid & 1) * 4;     // 0 or 4

    const float* Aptr = A + (size_t)(m0 + ldRow) * K + ldCol;
    const float* Wptr = W + (size_t)(n0 + ldRow) * K + ldCol;

    const int tm = (tid >> 4) * 4;       // 0..60
    const int tn = (tid & 15) * 4;       // 0..60

    unsigned long long acc[8][4];
#pragma unroll
    for (int i = 0; i < 8; ++i)
#pragma unroll
        for (int j = 0; j < 4; ++j) acc[i][j] = 0ULL;

    const int numTiles = K >> 3;

    // prologue: load tile 0 into buffer 0
    float4 aReg = *(const float4*)Aptr;
    float4 wReg = *(const float4*)Wptr;
    As[0][ldCol + 0][ldRow] = aReg.x; As[0][ldCol + 1][ldRow] = aReg.y;
    As[0][ldCol + 2][ldRow] = aReg.z; As[0][ldCol + 3][ldRow] = aReg.w;
    Bs[0][ldCol + 0][ldRow] = wReg.x; Bs[0][ldCol + 1][ldRow] = wReg.y;
    Bs[0][ldCol + 2][ldRow] = wReg.z; Bs[0][ldCol + 3][ldRow] = wReg.w;
    __syncthreads();

    for (int t = 0; t < numTiles; ++t) {
        const int buf = t & 1;
        if (t + 1 < numTiles) {
            aReg = *(const float4*)(Aptr + (size_t)(t + 1) * 8);
            wReg = *(const float4*)(Wptr + (size_t)(t + 1) * 8);
        }
#pragma unroll
        for (int kk = 0; kk < 8; ++kk) {
            const float4 a0 = *(const float4*)&As[buf][kk][tm];
            const float4 a1 = *(const float4*)&As[buf][kk][64 + tm];
            const float4 b0 = *(const float4*)&Bs[buf][kk][tn];
            const float4 b1 = *(const float4*)&Bs[buf][kk][64 + tn];
            unsigned long long bp[4];
            bp[0] = pk2(b0.x, b0.y); bp[1] = pk2(b0.z, b0.w);
            bp[2] = pk2(b1.x, b1.y); bp[3] = pk2(b1.z, b1.w);
            const float av[8] = {a0.x, a0.y, a0.z, a0.w, a1.x, a1.y, a1.z, a1.w};
#pragma unroll
            for (int i = 0; i < 8; ++i) {
                const unsigned long long ap = pk2(av[i], av[i]);
#pragma unroll
                for (int j = 0; j < 4; ++j) fma2(acc[i][j], ap, bp[j]);
            }
        }
        if (t + 1 < numTiles) {
            const int nb = buf ^ 1;
            As[nb][ldCol + 0][ldRow] = aReg.x; As[nb][ldCol + 1][ldRow] = aReg.y;
            As[nb][ldCol + 2][ldRow] = aReg.z; As[nb][ldCol + 3][ldRow] = aReg.w;
            Bs[nb][ldCol + 0][ldRow] = wReg.x; Bs[nb][ldCol + 1][ldRow] = wReg.y;
            Bs[nb][ldCol + 2][ldRow] = wReg.z; Bs[nb][ldCol + 3][ldRow] = wReg.w;
            __syncthreads();
        }
    }

    // epilogue
    float4 bb0 = make_float4(0.f, 0.f, 0.f, 0.f);
    float4 bb1 = make_float4(0.f, 0.f, 0.f, 0.f);
    if (BIAS) {
        bb0 = *(const float4*)&bias[n0 + tn];
        bb1 = *(const float4*)&bias[n0 + 64 + tn];
    }
#pragma unroll
    for (int i = 0; i < 8; ++i) {
        const int row = m0 + ((i < 4) ? (tm + i) : (64 + tm + (i - 4)));
        float c0, c1, c2, c3, c4, c5, c6, c7;
        upk2(acc[i][0], c0, c1); upk2(acc[i][1], c2, c3);
        upk2(acc[i][2], c4, c5); upk2(acc[i][3], c6, c7);
        if (BIAS) {
            c0 += bb0.x; c1 += bb0.y; c2 += bb0.z; c3 += bb0.w;
            c4 += bb1.x; c5 += bb1.y; c6 += bb1.z; c7 += bb1.w;
        }
        if (RELU) {
            c0 = fmaxf(c0, 0.f); c1 = fmaxf(c1, 0.f);
            c2 = fmaxf(c2, 0.f); c3 = fmaxf(c3, 0.f);
            c4 = fmaxf(c4, 0.f); c5 = fmaxf(c5, 0.f);
            c6 = fmaxf(c6, 0.f); c7 = fmaxf(c7, 0.f);
        }
        float* crow = C + (size_t)row * N;
        *(float4*)&crow[n0 + tn]      = make_float4(c0, c1, c2, c3);
        *(float4*)&crow[n0 + 64 + tn] = make_float4(c4, c5, c6, c7);
    }
}

// ---------------------------------------------------------------------------
// Pack sa = [state | action]  -> (B, 320)
// ---------------------------------------------------------------------------
__global__ void pack_sa_kernel(const float4* __restrict__ st,
                               const float4* __restrict__ ac,
                               float4* __restrict__ sa)
{
    const int idx = blockIdx.x * blockDim.x + threadIdx.x;   // over B*80 float4s
    if (idx >= BATCH * (INDIM / 4)) return;
    const int row = idx / 80;
    const int c   = idx - row * 80;
    sa[idx] = (c < 64) ? st[(size_t)row * 64 + c] : ac[(size_t)row * 16 + (c - 64)];
}

// ---------------------------------------------------------------------------
// GRU pointwise: consumes gi, gh, h, biases -> h_new (float4-vectorized)
// ---------------------------------------------------------------------------
__device__ __forceinline__ float sigm(float x) { return 1.f / (1.f + expf(-x)); }

__global__ void gru_pointwise(const float* __restrict__ gi,
                              const float* __restrict__ gh,
                              const float* __restrict__ h,
                              const float* __restrict__ b_ih,
                              const float* __restrict__ b_hh,
                              float* __restrict__ hnew)
{
    const int idx = blockIdx.x * blockDim.x + threadIdx.x;   // over B*128 float4s
    if (idx >= BATCH * (GDIM / 4)) return;
    const int b = idx >> 7;
    const int j = (idx & 127) << 2;
    const size_t gbase = (size_t)b * G3 + j;

    const float4 ir = *(const float4*)(gi + gbase);
    const float4 iz = *(const float4*)(gi + gbase + GDIM);
    const float4 in = *(const float4*)(gi + gbase + 2 * GDIM);
    const float4 hr = *(const float4*)(gh + gbase);
    const float4 hz = *(const float4*)(gh + gbase + GDIM);
    const float4 hn = *(const float4*)(gh + gbase + 2 * GDIM);

    const float4 bir = *(const float4*)(b_ih + j);
    const float4 biz = *(const float4*)(b_ih + GDIM + j);
    const float4 bin = *(const float4*)(b_ih + 2 * GDIM + j);
    const float4 bhr = *(const float4*)(b_hh + j);
    const float4 bhz = *(const float4*)(b_hh + GDIM + j);
    const float4 bhn = *(const float4*)(b_hh + 2 * GDIM + j);

    const float4 hp = *(const float4*)(h + (size_t)b * GDIM + j);

    float4 out;
    {
        const float r = sigm(ir.x + bir.x + hr.x + bhr.x);
        const float z = sigm(iz.x + biz.x + hz.x + bhz.x);
        const float n = tanhf(in.x + bin.x + r * (hn.x + bhn.x));
        out.x = (1.f - z) * n + z * hp.x;
    }
    {
        const float r = sigm(ir.y + bir.y + hr.y + bhr.y);
        const float z = sigm(iz.y + biz.y + hz.y + bhz.y);
        const float n = tanhf(in.y + bin.y + r * (hn.y + bhn.y));
        out.y = (1.f - z) * n + z * hp.y;
    }
    {
        const float r = sigm(ir.z + bir.z + hr.z + bhr.z);
        const float z = sigm(iz.z + biz.z + hz.z + bhz.z);
        const float n = tanhf(in.z + bin.z + r * (hn.z + bhn.z));
        out.z = (1.f - z) * n + z * hp.z;
    }
    {
        const float r = sigm(ir.w + bir.w + hr.w + bhr.w);
        const float z = sigm(iz.w + biz.w + hz.w + bhz.w);
        const float n = tanhf(in.w + bin.w + r * (hn.w + bhn.w));
        out.w = (1.f - z) * n + z * hp.w;
    }
    *(float4*)(hnew + (size_t)b * GDIM + j) = out;
}

// ---------------------------------------------------------------------------
// q = x2 @ w3^T + b3  (one warp per batch row)
// ---------------------------------------------------------------------------
__global__ void gemv_q(const float* __restrict__ x2, const float* __restrict__ w3,
                       const float* __restrict__ b3, float* __restrict__ q)
{
    const int warp = (blockIdx.x * blockDim.x + threadIdx.x) >> 5;
    const int lane = threadIdx.x & 31;
    if (warp >= BATCH) return;
    const float4* xr = (const float4*)(x2 + (size_t)warp * HDIM);
    const float4* w4 = (const float4*)w3;
    float s = 0.f;
#pragma unroll
    for (int i = 0; i < 8; ++i) {
        const float4 a = xr[lane + 32 * i];
        const float4 b = __ldg(&w4[lane + 32 * i]);
        s += a.x * b.x + a.y * b.y + a.z * b.z + a.w * b.w;
    }
#pragma unroll
    for (int o = 16; o; o >>= 1) s += __shfl_xor_sync(0xffffffffu, s, o);
    if (lane == 0) q[warp] = s + __ldg(b3);
}

// ---------------------------------------------------------------------------
extern "C" void kernel_launch(void* const* d_in, const int* in_sizes, int n_in,
                              void* d_out, int out_size)
{
    const float* state  = (const float*)d_in[0];
    const float* action = (const float*)d_in[1];
    const float* hidden = (const float*)d_in[2];   // (1,B,G) == (B,G)
    const float* w_ih   = (const float*)d_in[3];   // (1536,320)
    const float* w_hh   = (const float*)d_in[4];   // (1536,512)
    const float* b_ih   = (const float*)d_in[5];
    const float* b_hh   = (const float*)d_in[6];
    const float* w1     = (const float*)d_in[7];   // (1024,512)
    const float* b1     = (const float*)d_in[8];
    const float* w2     = (const float*)d_in[9];   // (1024,1024)
    const float* b2     = (const float*)d_in[10];
    const float* w3     = (const float*)d_in[11];  // (1,1024)
    const float* b3     = (const float*)d_in[12];

    float* q    = (float*)d_out;                   // first 65536 floats
    float* hnew = (float*)d_out + BATCH;           // then B*512 floats

    float *sa, *gi, *gh, *x1, *x2;
    cudaGetSymbolAddress((void**)&sa, g_sa);
    cudaGetSymbolAddress((void**)&gi, g_gi);
    cudaGetSymbolAddress((void**)&gh, g_gh);
    cudaGetSymbolAddress((void**)&x1, g_x1);
    cudaGetSymbolAddress((void**)&x2, g_x2);

    // 1) pack [state|action]
    {
        const int n = BATCH * (INDIM / 4);
        pack_sa_kernel<<<(n + 255) / 256, 256>>>((const float4*)state,
                                                 (const float4*)action,
                                                 (float4*)sa);
    }
    // 2) gi = sa @ w_ih^T      (B,1536) K=320
    sgemm_nt<false, false><<<dim3(G3 / 128, BATCH / 128), 256>>>(
        sa, w_ih, nullptr, gi, BATCH, G3, INDIM);
    // 3) gh = h @ w_hh^T       (B,1536) K=512
    sgemm_nt<false, false><<<dim3(G3 / 128, BATCH / 128), 256>>>(
        hidden, w_hh, nullptr, gh, BATCH, G3, GDIM);
    // 4) GRU gates -> h_new (written straight into d_out region)
    {
        const int n = BATCH * (GDIM / 4);
        gru_pointwise<<<(n + 255) / 256, 256>>>(gi, gh, hidden, b_ih, b_hh, hnew);
    }
    // 5) x1 = relu(h_new @ w1^T + b1)   (B,1024) K=512
    sgemm_nt<true, true><<<dim3(HDIM / 128, BATCH / 128), 256>>>(
        hnew, w1, b1, x1, BATCH, HDIM, GDIM);
    // 6) x2 = relu(x1 @ w2^T + b2)      (B,1024) K=1024
    sgemm_nt<true, true><<<dim3(HDIM / 128, BATCH / 128), 256>>>(
        x1, w2, b2, x2, BATCH, HDIM, HDIM);
    // 7) q = x2 @ w3^T + b3
    gemv_q<<<BATCH / 8, 256>>>(x2, w3, b3, q);
}

// round 14
// speedup vs baseline: 1.0009x; 1.0009x over previous
#include <cuda_runtime.h>
#include <cuda_bf16.h>
#include <cstdint>
#include <cstddef>

// ---------------------------------------------------------------------------
// QNetwork: GRU cell + 2-layer MLP head, B=65536
//   sa = [state|action]  (B,320)
//   gi = sa @ w_ih^T     (B,1536)
//   gh = h  @ w_hh^T     (B,1536)
//   r = sig(i_r+h_r+b), z = sig(i_z+h_z+b), n = tanh(i_n+b + r*(h_n+b))
//   h_new = (1-z)*n + z*h
//   x1 = relu(h_new@w1^T+b1); x2 = relu(x1@w2^T+b2); q = x2@w3^T+b3
// Outputs (flattened tuple concat): q (65536 floats) then h_new (65536*512).
// ---------------------------------------------------------------------------

#define BATCH   65536
#define SDIM    256
#define ADIM    64
#define INDIM   320
#define GDIM    512
#define HDIM    1024
#define G3      1536

// Scratch (no cudaMalloc allowed -> __device__ globals)
__device__ float g_sa[(size_t)BATCH * INDIM];
__device__ float g_gi[(size_t)BATCH * G3];
__device__ float g_gh[(size_t)BATCH * G3];
__device__ float g_x1[(size_t)BATCH * HDIM];
__device__ float g_x2[(size_t)BATCH * HDIM];

// ---------------- f32x2 packed-FMA helpers (FFMA2 path, sm_103a) ----------
__device__ __forceinline__ unsigned long long pk2(float lo, float hi) {
    unsigned long long r;
    asm("mov.b64 %0, {%1, %2};"
        : "=l"(r) : "r"(__float_as_uint(lo)), "r"(__float_as_uint(hi)));
    return r;
}
__device__ __forceinline__ void upk2(unsigned long long v, float& lo, float& hi) {
    unsigned int a, b;
    asm("mov.b64 {%0, %1}, %2;" : "=r"(a), "=r"(b) : "l"(v));
    lo = __uint_as_float(a);
    hi = __uint_as_float(b);
}
__device__ __forceinline__ void fma2(unsigned long long& d,
                                     unsigned long long a,
                                     unsigned long long b) {
    asm("fma.rn.f32x2 %0, %1, %2, %0;" : "+l"(d) : "l"(a), "l"(b));
}

// ---------------------------------------------------------------------------
// SGEMM (NT): C[M,N] = A[M,K] @ W[N,K]^T (+bias, +relu)
// BM=BN=128, BK=8, 256 threads, 8x8 microtile, double-buffered smem,
// inner product via packed f32x2 FMA (2 MACs / instr).
// Requires: M%128==0, N%128==0, K%8==0.
// ---------------------------------------------------------------------------
template <bool BIAS, bool RELU>
__global__ __launch_bounds__(256, 2)
void sgemm_nt(const float* __restrict__ A, const float* __restrict__ W,
              const float* __restrict__ bias, float* __restrict__ C,
              int M, int N, int K)
{
    __shared__ float As[2][8][132];
    __shared__ float Bs[2][8][132];

    const int tid = threadIdx.x;
    const int m0  = blockIdx.y * 128;
    const int n0  = blockIdx.x * 128;

    // gmem staging: each thread loads one float4 of A and one of W per tile
    const int ldRow = tid >> 1;          // 0..127
    const int ldCol = (tid & 1) * 4;     // 0 or 4

    const float* Aptr = A + (size_t)(m0 + ldRow) * K + ldCol;
    const float* Wptr = W + (size_t)(n0 + ldRow) * K + ldCol;

    const int tm = (tid >> 4) * 4;       // 0..60
    const int tn = (tid & 15) * 4;       // 0..60

    unsigned long long acc[8][4];
#pragma unroll
    for (int i = 0; i < 8; ++i)
#pragma unroll
        for (int j = 0; j < 4; ++j) acc[i][j] = 0ULL;

    const int numTiles = K >> 3;

    // prologue: load tile 0 into buffer 0
    float4 aReg = *(const float4*)Aptr;
    float4 wReg = *(const float4*)Wptr;
    As[0][ldCol + 0][ldRow] = aReg.x; As[0][ldCol + 1][ldRow] = aReg.y;
    As[0][ldCol + 2][ldRow] = aReg.z; As[0][ldCol + 3][ldRow] = aReg.w;
    Bs[0][ldCol + 0][ldRow] = wReg.x; Bs[0][ldCol + 1][ldRow] = wReg.y;
    Bs[0][ldCol + 2][ldRow] = wReg.z; Bs[0][ldCol + 3][ldRow] = wReg.w;
    __syncthreads();

    for (int t = 0; t < numTiles; ++t) {
        const int buf = t & 1;
        if (t + 1 < numTiles) {
            aReg = *(const float4*)(Aptr + (size_t)(t + 1) * 8);
            wReg = *(const float4*)(Wptr + (size_t)(t + 1) * 8);
        }
#pragma unroll
        for (int kk = 0; kk < 8; ++kk) {
            const float4 a0 = *(const float4*)&As[buf][kk][tm];
            const float4 a1 = *(const float4*)&As[buf][kk][64 + tm];
            const float4 b0 = *(const float4*)&Bs[buf][kk][tn];
            const float4 b1 = *(const float4*)&Bs[buf][kk][64 + tn];
            unsigned long long bp[4];
            bp[0] = pk2(b0.x, b0.y); bp[1] = pk2(b0.z, b0.w);
            bp[2] = pk2(b1.x, b1.y); bp[3] = pk2(b1.z, b1.w);
            const float av[8] = {a0.x, a0.y, a0.z, a0.w, a1.x, a1.y, a1.z, a1.w};
#pragma unroll
            for (int i = 0; i < 8; ++i) {
                const unsigned long long ap = pk2(av[i], av[i]);
#pragma unroll
                for (int j = 0; j < 4; ++j) fma2(acc[i][j], ap, bp[j]);
            }
        }
        if (t + 1 < numTiles) {
            const int nb = buf ^ 1;
            As[nb][ldCol + 0][ldRow] = aReg.x; As[nb][ldCol + 1][ldRow] = aReg.y;
            As[nb][ldCol + 2][ldRow] = aReg.z; As[nb][ldCol + 3][ldRow] = aReg.w;
            Bs[nb][ldCol + 0][ldRow] = wReg.x; Bs[nb][ldCol + 1][ldRow] = wReg.y;
            Bs[nb][ldCol + 2][ldRow] = wReg.z; Bs[nb][ldCol + 3][ldRow] = wReg.w;
            __syncthreads();
        }
    }

    // epilogue
    float4 bb0 = make_float4(0.f, 0.f, 0.f, 0.f);
    float4 bb1 = make_float4(0.f, 0.f, 0.f, 0.f);
    if (BIAS) {
        bb0 = *(const float4*)&bias[n0 + tn];
        bb1 = *(const float4*)&bias[n0 + 64 + tn];
    }
#pragma unroll
    for (int i = 0; i < 8; ++i) {
        const int row = m0 + ((i < 4) ? (tm + i) : (64 + tm + (i - 4)));
        float c0, c1, c2, c3, c4, c5, c6, c7;
        upk2(acc[i][0], c0, c1); upk2(acc[i][1], c2, c3);
        upk2(acc[i][2], c4, c5); upk2(acc[i][3], c6, c7);
        if (BIAS) {
            c0 += bb0.x; c1 += bb0.y; c2 += bb0.z; c3 += bb0.w;
            c4 += bb1.x; c5 += bb1.y; c6 += bb1.z; c7 += bb1.w;
        }
        if (RELU) {
            c0 = fmaxf(c0, 0.f); c1 = fmaxf(c1, 0.f);
            c2 = fmaxf(c2, 0.f); c3 = fmaxf(c3, 0.f);
            c4 = fmaxf(c4, 0.f); c5 = fmaxf(c5, 0.f);
            c6 = fmaxf(c6, 0.f); c7 = fmaxf(c7, 0.f);
        }
        float* crow = C + (size_t)row * N;
        *(float4*)&crow[n0 + tn]      = make_float4(c0, c1, c2, c3);
        *(float4*)&crow[n0 + 64 + tn] = make_float4(c4, c5, c6, c7);
    }
}

// ---------------------------------------------------------------------------
// Pack sa = [state | action]  -> (B, 320)
// ---------------------------------------------------------------------------
__global__ void pack_sa_kernel(const float4* __restrict__ st,
                               const float4* __restrict__ ac,
                               float4* __restrict__ sa)
{
    const int idx = blockIdx.x * blockDim.x + threadIdx.x;   // over B*80 float4s
    if (idx >= BATCH * (INDIM / 4)) return;
    const int row = idx / 80;
    const int c   = idx - row * 80;
    sa[idx] = (c < 64) ? st[(size_t)row * 64 + c] : ac[(size_t)row * 16 + (c - 64)];
}

// ---------------------------------------------------------------------------
// GRU pointwise: consumes gi, gh, h, biases -> h_new (float4-vectorized)
// ---------------------------------------------------------------------------
__device__ __forceinline__ float sigm(float x) { return 1.f / (1.f + expf(-x)); }

__global__ void gru_pointwise(const float* __restrict__ gi,
                              const float* __restrict__ gh,
                              const float* __restrict__ h,
                              const float* __restrict__ b_ih,
                              const float* __restrict__ b_hh,
                              float* __restrict__ hnew)
{
    const int idx = blockIdx.x * blockDim.x + threadIdx.x;   // over B*128 float4s
    if (idx >= BATCH * (GDIM / 4)) return;
    const int b = idx >> 7;
    const int j = (idx & 127) << 2;
    const size_t gbase = (size_t)b * G3 + j;

    const float4 ir = *(const float4*)(gi + gbase);
    const float4 iz = *(const float4*)(gi + gbase + GDIM);
    const float4 in = *(const float4*)(gi + gbase + 2 * GDIM);
    const float4 hr = *(const float4*)(gh + gbase);
    const float4 hz = *(const float4*)(gh + gbase + GDIM);
    const float4 hn = *(const float4*)(gh + gbase + 2 * GDIM);

    const float4 bir = *(const float4*)(b_ih + j);
    const float4 biz = *(const float4*)(b_ih + GDIM + j);
    const float4 bin = *(const float4*)(b_ih + 2 * GDIM + j);
    const float4 bhr = *(const float4*)(b_hh + j);
    const float4 bhz = *(const float4*)(b_hh + GDIM + j);
    const float4 bhn = *(const float4*)(b_hh + 2 * GDIM + j);

    const float4 hp = *(const float4*)(h + (size_t)b * GDIM + j);

    float4 out;
    {
        const float r = sigm(ir.x + bir.x + hr.x + bhr.x);
        const float z = sigm(iz.x + biz.x + hz.x + bhz.x);
        const float n = tanhf(in.x + bin.x + r * (hn.x + bhn.x));
        out.x = (1.f - z) * n + z * hp.x;
    }
    {
        const float r = sigm(ir.y + bir.y + hr.y + bhr.y);
        const float z = sigm(iz.y + biz.y + hz.y + bhz.y);
        const float n = tanhf(in.y + bin.y + r * (hn.y + bhn.y));
        out.y = (1.f - z) * n + z * hp.y;
    }
    {
        const float r = sigm(ir.z + bir.z + hr.z + bhr.z);
        const float z = sigm(iz.z + biz.z + hz.z + bhz.z);
        const float n = tanhf(in.z + bin.z + r * (hn.z + bhn.z));
        out.z = (1.f - z) * n + z * hp.z;
    }
    {
        const float r = sigm(ir.w + bir.w + hr.w + bhr.w);
        const float z = sigm(iz.w + biz.w + hz.w + bhz.w);
        const float n = tanhf(in.w + bin.w + r * (hn.w + bhn.w));
        out.w = (1.f - z) * n + z * hp.w;
    }
    *(float4*)(hnew + (size_t)b * GDIM + j) = out;
}

// ---------------------------------------------------------------------------
// q = x2 @ w3^T + b3  (one warp per batch row)
// ---------------------------------------------------------------------------
__global__ void gemv_q(const float* __restrict__ x2, const float* __restrict__ w3,
                       const float* __restrict__ b3, float* __restrict__ q)
{
    const int warp = (blockIdx.x * blockDim.x + threadIdx.x) >> 5;
    const int lane = threadIdx.x & 31;
    if (warp >= BATCH) return;
    const float4* xr = (const float4*)(x2 + (size_t)warp * HDIM);
    const float4* w4 = (const float4*)w3;
    float s = 0.f;
#pragma unroll
    for (int i = 0; i < 8; ++i) {
        const float4 a = xr[lane + 32 * i];
        const float4 b = __ldg(&w4[lane + 32 * i]);
        s += a.x * b.x + a.y * b.y + a.z * b.z + a.w * b.w;
    }
#pragma unroll
    for (int o = 16; o; o >>= 1) s += __shfl_xor_sync(0xffffffffu, s, o);
    if (lane == 0) q[warp] = s + __ldg(b3);
}

// ---------------------------------------------------------------------------
extern "C" void kernel_launch(void* const* d_in, const int* in_sizes, int n_in,
                              void* d_out, int out_size)
{
    const float* state  = (const float*)d_in[0];
    const float* action = (const float*)d_in[1];
    const float* hidden = (const float*)d_in[2];   // (1,B,G) == (B,G)
    const float* w_ih   = (const float*)d_in[3];   // (1536,320)
    const float* w_hh   = (const float*)d_in[4];   // (1536,512)
    const float* b_ih   = (const float*)d_in[5];
    const float* b_hh   = (const float*)d_in[6];
    const float* w1     = (const float*)d_in[7];   // (1024,512)
    const float* b1     = (const float*)d_in[8];
    const float* w2     = (const float*)d_in[9];   // (1024,1024)
    const float* b2     = (const float*)d_in[10];
    const float* w3     = (const float*)d_in[11];  // (1,1024)
    const float* b3     = (const float*)d_in[12];

    float* q    = (float*)d_out;                   // first 65536 floats
    float* hnew = (float*)d_out + BATCH;           // then B*512 floats

    float *sa, *gi, *gh, *x1, *x2;
    cudaGetSymbolAddress((void**)&sa, g_sa);
    cudaGetSymbolAddress((void**)&gi, g_gi);
    cudaGetSymbolAddress((void**)&gh, g_gh);
    cudaGetSymbolAddress((void**)&x1, g_x1);
    cudaGetSymbolAddress((void**)&x2, g_x2);

    // 1) pack [state|action]
    {
        const int n = BATCH * (INDIM / 4);
        pack_sa_kernel<<<(n + 255) / 256, 256>>>((const float4*)state,
                                                 (const float4*)action,
                                                 (float4*)sa);
    }
    // 2) gi = sa @ w_ih^T      (B,1536) K=320
    sgemm_nt<false, false><<<dim3(G3 / 128, BATCH / 128), 256>>>(
        sa, w_ih, nullptr, gi, BATCH, G3, INDIM);
    // 3) gh = h @ w_hh^T       (B,1536) K=512
    sgemm_nt<false, false><<<dim3(G3 / 128, BATCH / 128), 256>>>(
        hidden, w_hh, nullptr, gh, BATCH, G3, GDIM);
    // 4) GRU gates -> h_new (written straight into d_out region)
    {
        const int n = BATCH * (GDIM / 4);
        gru_pointwise<<<(n + 255) / 256, 256>>>(gi, gh, hidden, b_ih, b_hh, hnew);
    }
    // 5) x1 = relu(h_new @ w1^T + b1)   (B,1024) K=512
    sgemm_nt<true, true><<<dim3(HDIM / 128, BATCH / 128), 256>>>(
        hnew, w1, b1, x1, BATCH, HDIM, GDIM);
    // 6) x2 = relu(x1 @ w2^T + b2)      (B,1024) K=1024
    sgemm_nt<true, true><<<dim3(HDIM / 128, BATCH / 128), 256>>>(
        x1, w2, b2, x2, BATCH, HDIM, HDIM);
    // 7) q = x2 @ w3^T + b3
    gemv_q<<<BATCH / 8, 256>>>(x2, w3, b3, q);
}

// round 17
// speedup vs baseline: 4.7906x; 4.7861x over previous
#include <cuda_runtime.h>
#include <cuda_fp16.h>
#include <cstdint>
#include <cstddef>

// ---------------------------------------------------------------------------
// QNetwork, fp16 GEMMs on mma.sync (HMMA.16816, fp32 accum) — sm_103 baseline
// ISA only (no tcgen05: harness ptxas targets sm_103 without the 'a' suffix).
//   sa = [state|action] (B,320) -> gi = sa @ w_ih^T (B,1536)
//   gh = h @ w_hh^T (B,1536) -> GRU pointwise -> h_new
//   x1 = relu(h_new@w1^T+b1) ; x2 = relu(x1@w2^T+b2) ; q = x2@w3^T+b3
// Output: q (65536 f32) then h_new (65536*512 f32).
// ---------------------------------------------------------------------------

#define BATCH 65536
#define INDIM 320
#define GDIM  512
#define HDIM  1024
#define G3    1536

// ---------------- fp16 scratch (__device__ globals; no cudaMalloc) ---------
__device__ __half g_sa16 [(size_t)BATCH * INDIM];
__device__ __half g_h16  [(size_t)BATCH * GDIM];
__device__ __half g_gi16 [(size_t)BATCH * G3];
__device__ __half g_gh16 [(size_t)BATCH * G3];
__device__ __half g_hn16 [(size_t)BATCH * GDIM];
__device__ __half g_x116 [(size_t)BATCH * HDIM];
__device__ __half g_x216 [(size_t)BATCH * HDIM];
__device__ __half g_wih16[(size_t)G3 * INDIM];
__device__ __half g_whh16[(size_t)G3 * GDIM];
__device__ __half g_w116 [(size_t)HDIM * GDIM];
__device__ __half g_w216 [(size_t)HDIM * HDIM];
__device__ __half g_w316 [HDIM];

// ---------------------------- PTX helpers ----------------------------------
__device__ __forceinline__ uint32_t smem_u32(const void* p) {
    uint32_t a;
    asm("{ .reg .u64 t; cvta.to.shared.u64 t, %1; cvt.u32.u64 %0, t; }"
        : "=r"(a) : "l"(p));
    return a;
}
__device__ __forceinline__ void cp_async16(uint32_t dst, const void* src) {
    asm volatile("cp.async.cg.shared.global [%0], [%1], 16;" :: "r"(dst), "l"(src));
}
__device__ __forceinline__ void cp_commit() {
    asm volatile("cp.async.commit_group;" ::: "memory");
}
__device__ __forceinline__ void cp_wait2() {
    asm volatile("cp.async.wait_group 2;" ::: "memory");
}
__device__ __forceinline__ void cp_wait0() {
    asm volatile("cp.async.wait_group 0;" ::: "memory");
}
__device__ __forceinline__ void ldsm_x4(uint32_t& r0, uint32_t& r1,
                                        uint32_t& r2, uint32_t& r3, uint32_t addr) {
    asm volatile("ldmatrix.sync.aligned.m8n8.x4.shared.b16 {%0,%1,%2,%3}, [%4];"
                 : "=r"(r0), "=r"(r1), "=r"(r2), "=r"(r3) : "r"(addr));
}
__device__ __forceinline__ void mma16816(float* c, const uint32_t* a,
                                         const uint32_t* b) {
    asm volatile(
        "mma.sync.aligned.m16n8k16.row.col.f32.f16.f16.f32 "
        "{%0,%1,%2,%3}, {%4,%5,%6,%7}, {%8,%9}, {%0,%1,%2,%3};"
        : "+f"(c[0]), "+f"(c[1]), "+f"(c[2]), "+f"(c[3])
        : "r"(a[0]), "r"(a[1]), "r"(a[2]), "r"(a[3]), "r"(b[0]), "r"(b[1]));
}

// ---------------------------------------------------------------------------
// GEMM (NT): C16[M,N] = A16[M,K] @ W16[N,K]^T (+bias,+relu), fp16 out.
// CTA 128x128x64, 4-stage cp.async, 8 warps (4m x 2n), warp tile 32x64.
// Requires M%128==0, N%128==0, K%64==0, K/64 >= 3.
// ---------------------------------------------------------------------------
#define STAGES    4
#define BM        128
#define BN        128
#define BK        64
#define A_STAGE_B 16384            // 128*64*2
#define STAGE_B   32768            // A + B
#define GEMM_SMEM (STAGES * STAGE_B + 1024)
#define EP_LD     136              // epilogue smem row stride (halves)

template <bool BIASRELU>
__global__ __launch_bounds__(256, 1)
void gemm_f16(const __half* __restrict__ A, const __half* __restrict__ W,
              const float* __restrict__ bias, __half* __restrict__ C,
              int M, int N, int K)
{
    extern __shared__ char dsm[];
    uint32_t sb = smem_u32(dsm);
    const uint32_t pad = (1024u - (sb & 1023u)) & 1023u;
    sb += pad;                                   // 1024B align (swizzle base)
    __half* ep = reinterpret_cast<__half*>(dsm + pad);

    const int tid  = threadIdx.x;
    const int wid  = tid >> 5;
    const int lane = tid & 31;
    const int wm   = wid & 3;                    // warp m index (0..3)
    const int wn   = wid >> 2;                   // warp n index (0..1)
    const int m0   = blockIdx.y * BM;
    const int n0   = blockIdx.x * BN;
    const int numK = K / BK;

    // per-stage tile loader: 16B cp.async chunks, chunk ^= row&7 swizzle
    auto load_stage = [&](int t, int buf) {
        const uint32_t sA = sb + buf * STAGE_B;
        const uint32_t sB = sA + A_STAGE_B;
        const int k0 = t * BK;
#pragma unroll
        for (int i = 0; i < 4; ++i) {            // A: 1024 chunks
            const int q = tid + i * 256;
            const int row = q >> 3, c = q & 7;
            cp_async16(sA + row * 128 + ((c ^ (row & 7)) << 4),
                       A + (size_t)(m0 + row) * K + k0 + c * 8);
        }
#pragma unroll
        for (int i = 0; i < 4; ++i) {            // B: 1024 chunks
            const int q = tid + i * 256;
            const int row = q >> 3, c = q & 7;
            cp_async16(sB + row * 128 + ((c ^ (row & 7)) << 4),
                       W + (size_t)(n0 + row) * K + k0 + c * 8);
        }
        cp_commit();
    };

    float acc[2][8][4];
#pragma unroll
    for (int mt = 0; mt < 2; ++mt)
#pragma unroll
        for (int nt = 0; nt < 8; ++nt)
#pragma unroll
            for (int e = 0; e < 4; ++e) acc[mt][nt][e] = 0.f;

    // prologue: stages 0..2
    for (int p = 0; p < STAGES - 1; ++p) load_stage(p, p);

    // precomputed lane geometry
    const int rowA_lo = (lane & 15);             // + m-tile base
    const int chA_bit = lane >> 4;               // k-chunk bit for A
    const int rowB_lo = (lane & 7) + ((lane >> 4) << 3);
    const int chB_bit = (lane >> 3) & 1;         // k-chunk bit for B

    for (int t = 0; t < numK; ++t) {
        cp_wait2();                              // stage t resident
        __syncthreads();

        const int buf = t & (STAGES - 1);
        const uint32_t sA = sb + buf * STAGE_B;
        const uint32_t sB = sA + A_STAGE_B;

#pragma unroll
        for (int s = 0; s < 4; ++s) {            // 4 x k16 steps
            uint32_t a[2][4];
#pragma unroll
            for (int mt = 0; mt < 2; ++mt) {
                const int r = wm * 32 + mt * 16 + rowA_lo;
                const int ch = 2 * s + chA_bit;
                ldsm_x4(a[mt][0], a[mt][1], a[mt][2], a[mt][3],
                        sA + r * 128 + (((ch ^ (r & 7))) << 4));
            }
            uint32_t b[8][2];
#pragma unroll
            for (int nt2 = 0; nt2 < 4; ++nt2) {  // each x4 covers two n8 tiles
                const int r = wn * 64 + nt2 * 16 + rowB_lo;
                const int ch = 2 * s + chB_bit;
                ldsm_x4(b[nt2 * 2][0], b[nt2 * 2][1],
                        b[nt2 * 2 + 1][0], b[nt2 * 2 + 1][1],
                        sB + r * 128 + (((ch ^ (r & 7))) << 4));
            }
#pragma unroll
            for (int mt = 0; mt < 2; ++mt)
#pragma unroll
                for (int nt = 0; nt < 8; ++nt)
                    mma16816(acc[mt][nt], a[mt], b[nt]);
        }

        const int nxt = t + STAGES - 1;
        if (nxt < numK) load_stage(nxt, nxt & (STAGES - 1));
        else            cp_commit();             // keep group count uniform
    }

    cp_wait0();
    __syncthreads();                             // safe to reuse smem

    // ---- epilogue: bias+relu on f32, stage fp16 tile in smem, coalesce out
    const int lq = lane >> 2;                    // row-in-8
    const int lr = (lane & 3) * 2;               // col pair
    float bv[8][2];
    if (BIASRELU) {
#pragma unroll
        for (int nt = 0; nt < 8; ++nt) {
            const int cg = n0 + wn * 64 + nt * 8 + lr;
            bv[nt][0] = __ldg(&bias[cg]);
            bv[nt][1] = __ldg(&bias[cg + 1]);
        }
    }
#pragma unroll
    for (int mt = 0; mt < 2; ++mt) {
        const int rl = wm * 32 + mt * 16 + lq;
#pragma unroll
        for (int nt = 0; nt < 8; ++nt) {
            const int nl = wn * 64 + nt * 8 + lr;
            float c0 = acc[mt][nt][0], c1 = acc[mt][nt][1];
            float c2 = acc[mt][nt][2], c3 = acc[mt][nt][3];
            if (BIASRELU) {
                c0 = fmaxf(c0 + bv[nt][0], 0.f);
                c1 = fmaxf(c1 + bv[nt][1], 0.f);
                c2 = fmaxf(c2 + bv[nt][0], 0.f);
                c3 = fmaxf(c3 + bv[nt][1], 0.f);
            }
            *reinterpret_cast<__half2*>(&ep[rl * EP_LD + nl]) =
                __floats2half2_rn(c0, c1);
            *reinterpret_cast<__half2*>(&ep[(rl + 8) * EP_LD + nl]) =
                __floats2half2_rn(c2, c3);
        }
    }
    __syncthreads();
#pragma unroll
    for (int i = 0; i < 8; ++i) {                // 2048 uint4 total
        const int idx = tid + i * 256;
        const int row = idx >> 4, c16 = idx & 15;
        uint4 v = *reinterpret_cast<const uint4*>(&ep[row * EP_LD + c16 * 8]);
        *reinterpret_cast<uint4*>(C + (size_t)(m0 + row) * N + n0 + c16 * 8) = v;
    }
}

// ---------------------------------------------------------------------------
// Pointwise / conversion kernels
// ---------------------------------------------------------------------------
__device__ __forceinline__ void ld4h(const __half* p, float* f) {
    uint2 u = *(const uint2*)p;
    __half2 a = *reinterpret_cast<__half2*>(&u.x);
    __half2 b = *reinterpret_cast<__half2*>(&u.y);
    float2 fa = __half22float2(a), fb = __half22float2(b);
    f[0] = fa.x; f[1] = fa.y; f[2] = fb.x; f[3] = fb.y;
}
__device__ __forceinline__ void ld4f(const float* p, float* f) {
    float4 v = *(const float4*)p;
    f[0] = v.x; f[1] = v.y; f[2] = v.z; f[3] = v.w;
}
__device__ __forceinline__ float sigm(float x) { return 1.f / (1.f + expf(-x)); }

__global__ void cvt16(const float* __restrict__ in, __half* __restrict__ out, int n4)
{
    const int idx = blockIdx.x * blockDim.x + threadIdx.x;
    if (idx >= n4) return;
    float4 v = ((const float4*)in)[idx];
    __half2 a = __floats2half2_rn(v.x, v.y);
    __half2 b = __floats2half2_rn(v.z, v.w);
    uint2 u;
    u.x = *reinterpret_cast<uint32_t*>(&a);
    u.y = *reinterpret_cast<uint32_t*>(&b);
    ((uint2*)out)[idx] = u;
}

__global__ void pack_sa16(const float* __restrict__ st, const float* __restrict__ ac,
                          __half* __restrict__ sa)
{
    const int idx = blockIdx.x * blockDim.x + threadIdx.x;   // B*40 chunks of 8
    if (idx >= BATCH * 40) return;
    const int row = idx / 40;
    const int c   = idx - row * 40;
    const float* src = (c < 32) ? st + (size_t)row * 256 + c * 8
                                : ac + (size_t)row * 64 + (c - 32) * 8;
    float4 v0 = ((const float4*)src)[0];
    float4 v1 = ((const float4*)src)[1];
    __half2 a = __floats2half2_rn(v0.x, v0.y), b = __floats2half2_rn(v0.z, v0.w);
    __half2 c2 = __floats2half2_rn(v1.x, v1.y), d = __floats2half2_rn(v1.z, v1.w);
    uint4 u;
    u.x = *reinterpret_cast<uint32_t*>(&a);
    u.y = *reinterpret_cast<uint32_t*>(&b);
    u.z = *reinterpret_cast<uint32_t*>(&c2);
    u.w = *reinterpret_cast<uint32_t*>(&d);
    ((uint4*)sa)[idx] = u;
}

__global__ void gru_pointwise(const __half* __restrict__ gi, const __half* __restrict__ gh,
                              const float* __restrict__ h,
                              const float* __restrict__ b_ih, const float* __restrict__ b_hh,
                              float* __restrict__ hnew, __half* __restrict__ hnew16)
{
    const int idx = blockIdx.x * blockDim.x + threadIdx.x;   // B*(512/4)
    if (idx >= BATCH * (GDIM / 4)) return;
    const int b = idx >> 7;
    const int j = (idx & 127) << 2;
    const size_t gb = (size_t)b * G3 + j;

    float ir[4], iz[4], inn[4], hr[4], hz[4], hn[4];
    ld4h(gi + gb, ir); ld4h(gi + gb + GDIM, iz); ld4h(gi + gb + 2 * GDIM, inn);
    ld4h(gh + gb, hr); ld4h(gh + gb + GDIM, hz); ld4h(gh + gb + 2 * GDIM, hn);

    float bir[4], biz[4], bin[4], bhr[4], bhz[4], bhn[4], hp[4];
    ld4f(b_ih + j, bir); ld4f(b_ih + GDIM + j, biz); ld4f(b_ih + 2 * GDIM + j, bin);
    ld4f(b_hh + j, bhr); ld4f(b_hh + GDIM + j, bhz); ld4f(b_hh + 2 * GDIM + j, bhn);
    ld4f(h + (size_t)b * GDIM + j, hp);

    float o[4];
#pragma unroll
    for (int u = 0; u < 4; ++u) {
        const float r = sigm(ir[u] + bir[u] + hr[u] + bhr[u]);
        const float z = sigm(iz[u] + biz[u] + hz[u] + bhz[u]);
        const float n = tanhf(inn[u] + bin[u] + r * (hn[u] + bhn[u]));
        o[u] = (1.f - z) * n + z * hp[u];
    }
    *(float4*)(hnew + (size_t)b * GDIM + j) = make_float4(o[0], o[1], o[2], o[3]);
    __half2 p0 = __floats2half2_rn(o[0], o[1]);
    __half2 p1 = __floats2half2_rn(o[2], o[3]);
    uint2 u2;
    u2.x = *reinterpret_cast<uint32_t*>(&p0);
    u2.y = *reinterpret_cast<uint32_t*>(&p1);
    *(uint2*)(hnew16 + (size_t)b * GDIM + j) = u2;
}

__global__ void gemv_q(const __half* __restrict__ x2, const __half* __restrict__ w3,
                       const float* __restrict__ b3, float* __restrict__ q)
{
    const int warp = (blockIdx.x * blockDim.x + threadIdx.x) >> 5;
    const int lane = threadIdx.x & 31;
    if (warp >= BATCH) return;
    const uint4* xr = (const uint4*)(x2 + (size_t)warp * HDIM);
    const uint4* wr = (const uint4*)w3;
    float s = 0.f;
#pragma unroll
    for (int i = 0; i < 4; ++i) {
        uint4 ux = xr[lane + 32 * i];
        uint4 uw = __ldg(&wr[lane + 32 * i]);
        const uint32_t* px = &ux.x;
        const uint32_t* pw = &uw.x;
#pragma unroll
        for (int k = 0; k < 4; ++k) {
            float2 a = __half22float2(*reinterpret_cast<const __half2*>(&px[k]));
            float2 b = __half22float2(*reinterpret_cast<const __half2*>(&pw[k]));
            s += a.x * b.x + a.y * b.y;
        }
    }
#pragma unroll
    for (int o = 16; o; o >>= 1) s += __shfl_xor_sync(0xffffffffu, s, o);
    if (lane == 0) q[warp] = s + __ldg(b3);
}

// ---------------------------------------------------------------------------
extern "C" void kernel_launch(void* const* d_in, const int* in_sizes, int n_in,
                              void* d_out, int out_size)
{
    const float* state  = (const float*)d_in[0];
    const float* action = (const float*)d_in[1];
    const float* hidden = (const float*)d_in[2];
    const float* w_ih   = (const float*)d_in[3];
    const float* w_hh   = (const float*)d_in[4];
    const float* b_ih   = (const float*)d_in[5];
    const float* b_hh   = (const float*)d_in[6];
    const float* w1     = (const float*)d_in[7];
    const float* b1     = (const float*)d_in[8];
    const float* w2     = (const float*)d_in[9];
    const float* b2     = (const float*)d_in[10];
    const float* w3     = (const float*)d_in[11];
    const float* b3     = (const float*)d_in[12];

    float* q    = (float*)d_out;
    float* hnew = (float*)d_out + BATCH;

    __half *sa16, *h16, *gi16, *gh16, *hn16, *x116, *x216;
    __half *wih16, *whh16, *w116, *w216, *w316;
    cudaGetSymbolAddress((void**)&sa16,  g_sa16);
    cudaGetSymbolAddress((void**)&h16,   g_h16);
    cudaGetSymbolAddress((void**)&gi16,  g_gi16);
    cudaGetSymbolAddress((void**)&gh16,  g_gh16);
    cudaGetSymbolAddress((void**)&hn16,  g_hn16);
    cudaGetSymbolAddress((void**)&x116,  g_x116);
    cudaGetSymbolAddress((void**)&x216,  g_x216);
    cudaGetSymbolAddress((void**)&wih16, g_wih16);
    cudaGetSymbolAddress((void**)&whh16, g_whh16);
    cudaGetSymbolAddress((void**)&w116,  g_w116);
    cudaGetSymbolAddress((void**)&w216,  g_w216);
    cudaGetSymbolAddress((void**)&w316,  g_w316);

    cudaFuncSetAttribute(gemm_f16<false>, cudaFuncAttributeMaxDynamicSharedMemorySize, GEMM_SMEM);
    cudaFuncSetAttribute(gemm_f16<true>,  cudaFuncAttributeMaxDynamicSharedMemorySize, GEMM_SMEM);

    // fp32 -> fp16 conversions
    pack_sa16<<<(BATCH * 40 + 255) / 256, 256>>>(state, action, sa16);
    cvt16<<<(BATCH * GDIM / 4 + 255) / 256, 256>>>(hidden, h16, BATCH * GDIM / 4);
    cvt16<<<(G3 * INDIM / 4 + 255) / 256, 256>>>(w_ih, wih16, G3 * INDIM / 4);
    cvt16<<<(G3 * GDIM / 4 + 255) / 256, 256>>>(w_hh, whh16, G3 * GDIM / 4);
    cvt16<<<(HDIM * GDIM / 4 + 255) / 256, 256>>>(w1, w116, HDIM * GDIM / 4);
    cvt16<<<(HDIM * HDIM / 4 + 255) / 256, 256>>>(w2, w216, HDIM * HDIM / 4);
    cvt16<<<1, 256>>>(w3, w316, HDIM / 4);

    // gi = sa @ w_ih^T  (K=320)
    gemm_f16<false><<<dim3(G3 / BN, BATCH / BM), 256, GEMM_SMEM>>>(
        sa16, wih16, nullptr, gi16, BATCH, G3, INDIM);
    // gh = h @ w_hh^T   (K=512)
    gemm_f16<false><<<dim3(G3 / BN, BATCH / BM), 256, GEMM_SMEM>>>(
        h16, whh16, nullptr, gh16, BATCH, G3, GDIM);
    // GRU pointwise -> h_new (fp32 straight to d_out) + fp16 copy
    gru_pointwise<<<(BATCH * GDIM / 4 + 255) / 256, 256>>>(
        gi16, gh16, hidden, b_ih, b_hh, hnew, hn16);
    // x1 = relu(h_new @ w1^T + b1)  (K=512)
    gemm_f16<true><<<dim3(HDIM / BN, BATCH / BM), 256, GEMM_SMEM>>>(
        hn16, w116, b1, x116, BATCH, HDIM, GDIM);
    // x2 = relu(x1 @ w2^T + b2)     (K=1024)
    gemm_f16<true><<<dim3(HDIM / BN, BATCH / BM), 256, GEMM_SMEM>>>(
        x116, w216, b2, x216, BATCH, HDIM, HDIM);
    // q = x2 @ w3^T + b3
    gemv_q<<<BATCH / 8, 256>>>(x216, w316, b3, q);
}